// round 13
// baseline (speedup 1.0000x reference)
#include <cuda_runtime.h>
#include <cstdint>
#include <math.h>

// Problem constants
#define BB   8
#define NPT  8192
#define MPT  2048
#define CCH  256
#define CPCH 256
#define KD1  512
#define OC   256
#define NPOINTS (BB * NPT)   // 65536
#define BN_EPS 1e-5f
#define NMBLK (NPOINTS / 256)   // 256 m-blocks of 256 points
#define NT1  16                 // K-chunks GEMM1 (512/32)
#define NT2  8                  // K-chunks GEMM2 (256/32)
#define RING 3

#if defined(__CUDA_ARCH_FEAT_SM103_ALL) || defined(__CUDA_ARCH_FEAT_SM100_ALL)
#define HAS_TCGEN05 1
#else
#define HAS_TCGEN05 0
#endif

// ---------------- scratch (device globals; no allocs allowed) ----------------
// Swizzled tile images: block = [256 rows][32 k-words], 32KB, SW128 per 128B row.
__device__ __align__(16) uint32_t g_A1[(size_t)NMBLK * NT1 * 8192];  // tf32
__device__ __align__(16) uint32_t g_A2[(size_t)NMBLK * NT2 * 8192];  // fp32 pre-BN
__device__ __align__(16) uint32_t g_W1t[NT1 * 8192];
__device__ __align__(16) uint32_t g_W2t[NT2 * 8192];
__device__ __align__(16) float g_fpT[(size_t)BB * MPT * CPCH];       // features_prev^T [b][m][c]
__device__ int   g_idx[(size_t)NPOINTS * 3];
__device__ float g_wgt[(size_t)NPOINTS * 3];
__device__ __align__(16) float g_stats[4 * 256];
__device__ __align__(16) float g_bnA[2 * 256];
__device__ __align__(16) float g_bnC[2 * 256];

// ---------------- helpers ----------------
__device__ __forceinline__ uint32_t smem_u32(const void* p) {
    uint32_t a;
    asm("{ .reg .u64 t; cvta.to.shared.u64 t, %1; cvt.u32.u64 %0, t; }" : "=r"(a) : "l"(p));
    return a;
}
__device__ __host__ __forceinline__ uint32_t swz(uint32_t o) { return o ^ ((o >> 3) & 0x70); }
__device__ __forceinline__ uint32_t f2tf(float f) {
    uint32_t r; asm("cvt.rna.tf32.f32 %0, %1;" : "=r"(r) : "f"(f)); return r;
}

#if HAS_TCGEN05
__device__ __forceinline__ uint32_t elect1() {
    uint32_t p;
    asm volatile("{ .reg .pred p; elect.sync _|p, 0xFFFFFFFF; selp.b32 %0,1,0,p; }" : "=r"(p));
    return p;
}
static constexpr uint64_t DESC_BASE =
    (2ull << 61) | (1ull << 46) | (64ull << 32) | (1ull << 16);   // SW128, Blackwell, SBO=64, LBO=1
__device__ __forceinline__ uint64_t mk_desc(uint32_t a) {
    return DESC_BASE | (uint64_t)((a >> 4) & 0x3FFF);
}
__device__ __forceinline__ void mma_tf32(uint32_t d, uint64_t a, uint64_t b,
                                         uint32_t idesc, uint32_t en) {
    asm volatile(
        "{\n\t.reg .pred p;\n\tsetp.ne.u32 p, %5, 0;\n\t"
        "tcgen05.mma.cta_group::1.kind::tf32 [%0], %1, %2, %3, {%4, %4, %4, %4}, p;\n\t}"
        :: "r"(d), "l"(a), "l"(b), "r"(idesc), "r"(0u), "r"(en) : "memory");
}
__device__ __forceinline__ void mbar_wait(uint32_t mbar, uint32_t parity) {
    asm volatile(
        "{\n\t.reg .pred P;\n\tLW_%=:\n\t"
        "mbarrier.try_wait.parity.acquire.cta.shared::cta.b64 P, [%0], %1, 0x989680;\n\t"
        "@P bra.uni LD_%=;\n\tbra.uni LW_%=;\n\tLD_%=:\n\t}"
        :: "r"(mbar), "r"(parity) : "memory");
}
__device__ __forceinline__ void bulk_g2s(uint32_t dst, const void* src, uint32_t bytes,
                                         uint32_t mbar) {
    asm volatile(
        "cp.async.bulk.shared::cluster.global.mbarrier::complete_tx::bytes [%0], [%1], %2, [%3];"
        :: "r"(dst), "l"(src), "r"(bytes), "r"(mbar) : "memory");
}
__device__ __forceinline__ void ldtm32(uint32_t* r, uint32_t addr) {
    asm volatile(
        "tcgen05.ld.sync.aligned.32x32b.x32.b32 "
        "{%0, %1, %2, %3, %4, %5, %6, %7, %8, %9, %10, %11, %12, %13, %14, %15, "
        " %16, %17, %18, %19, %20, %21, %22, %23, %24, %25, %26, %27, %28, %29, %30, %31}, [%32];"
        : "=r"(r[0]), "=r"(r[1]), "=r"(r[2]), "=r"(r[3]), "=r"(r[4]), "=r"(r[5]),
          "=r"(r[6]), "=r"(r[7]), "=r"(r[8]), "=r"(r[9]), "=r"(r[10]), "=r"(r[11]),
          "=r"(r[12]), "=r"(r[13]), "=r"(r[14]), "=r"(r[15]), "=r"(r[16]), "=r"(r[17]),
          "=r"(r[18]), "=r"(r[19]), "=r"(r[20]), "=r"(r[21]), "=r"(r[22]), "=r"(r[23]),
          "=r"(r[24]), "=r"(r[25]), "=r"(r[26]), "=r"(r[27]), "=r"(r[28]), "=r"(r[29]),
          "=r"(r[30]), "=r"(r[31])
        : "r"(addr));
}
#endif  // HAS_TCGEN05

// ================ MEGA PREP: three_nn | transpose_fp | w_prep | zero | feat_prep ================
#define NB_3NN  256
#define NB_TFP  4096
#define NB_MISC 25            // 16 w1 + 8 w2 + 1 zero
#define NB_FEAT 16384
#define NB_TOTAL (NB_3NN + NB_TFP + NB_MISC + NB_FEAT)   // 20761

__global__ void __launch_bounds__(256) k_prep(
    const float* __restrict__ xyz, const float* __restrict__ xyzp,
    const float* __restrict__ featp, const float* __restrict__ feat,
    const float* __restrict__ w1, const float* __restrict__ w2) {
    __shared__ __align__(16) char sm[32768];
    const int blk = blockIdx.x;
    const int tid = threadIdx.x;

    if (blk < NB_3NN) {
        // ---- three_nn ----
        float4* sk = (float4*)sm;
        const int b = blk >> 5;
        const int n = (blk & 31) * 256 + tid;
        const float* kp = xyzp + (size_t)b * MPT * 3;
        for (int m = tid; m < MPT; m += 256) {
            float kx = kp[3 * m], ky = kp[3 * m + 1], kz = kp[3 * m + 2];
            sk[m] = make_float4(kx, ky, kz, kx * kx + ky * ky + kz * kz);
        }
        __syncthreads();
        const float* up = xyz + (size_t)(b * NPT + n) * 3;
        float ux = up[0], uy = up[1], uz = up[2];
        float squ = ux * ux + uy * uy + uz * uz;
        float d0 = 3.4e38f, d1 = 3.4e38f, d2 = 3.4e38f;
        int i0 = 0, i1 = 0, i2 = 0;
        for (int m = 0; m < MPT; m++) {
            float4 k = sk[m];
            float dot = fmaf(ux, k.x, fmaf(uy, k.y, uz * k.z));
            float dd = squ + k.w - 2.0f * dot;
            if (dd < d2) {
                if (dd < d1) {
                    d2 = d1; i2 = i1;
                    if (dd < d0) { d1 = d0; i1 = i0; d0 = dd; i0 = m; }
                    else         { d1 = dd; i1 = m; }
                } else { d2 = dd; i2 = m; }
            }
        }
        float s0 = sqrtf(fmaxf(d0, 0.f)), s1 = sqrtf(fmaxf(d1, 0.f)), s2 = sqrtf(fmaxf(d2, 0.f));
        float w0 = 1.0f / (s0 + 1e-8f), wq1 = 1.0f / (s1 + 1e-8f), wq2 = 1.0f / (s2 + 1e-8f);
        float ws = w0 + wq1 + wq2;
        size_t o = (size_t)(b * NPT + n) * 3;
        g_idx[o] = i0; g_idx[o + 1] = i1; g_idx[o + 2] = i2;
        g_wgt[o] = w0 / ws; g_wgt[o + 1] = wq1 / ws; g_wgt[o + 2] = wq2 / ws;
    } else if (blk < NB_3NN + NB_TFP) {
        // ---- transpose features_prev [b][c][m] -> g_fpT [b][m][c] ----
        const int idx = blk - NB_3NN;
        const int m0 = (idx & 63) * 32;
        const int c0 = ((idx >> 6) & 7) * 32;
        const int b = idx >> 9;
        float (*tile)[33] = (float(*)[33])sm;
        const int tx = tid & 31, ty = tid >> 5;   // 32 x 8
        const float* src = featp + (size_t)b * CPCH * MPT;
        #pragma unroll
        for (int j = 0; j < 32; j += 8)
            tile[ty + j][tx] = src[(size_t)(c0 + ty + j) * MPT + m0 + tx];
        __syncthreads();
        float* dst = g_fpT + (size_t)b * MPT * CPCH;
        #pragma unroll
        for (int j = 0; j < 32; j += 8)
            dst[(size_t)(m0 + ty + j) * CPCH + c0 + tx] = tile[tx][ty + j];
    } else if (blk < NB_3NN + NB_TFP + NB_MISC) {
        const int idx = blk - NB_3NN - NB_TFP;
        if (idx < 24) {
            // ---- w_prep: swizzled tf32 weight tiles ----
            const int t = (idx < 16) ? idx : (idx - 16);
            const float* W = (idx < 16) ? w1 : w2;
            const int K = (idx < 16) ? KD1 : OC;
            uint32_t* dst = (idx < 16) ? g_W1t : g_W2t;
            #pragma unroll
            for (int i = 0; i < 8; i++) {
                const int f = tid + i * 256;
                const int row = f >> 3, wq = f & 7;
                const float4 v = *(const float4*)(W + (size_t)row * K + t * 32 + wq * 4);
                uint4 tv = make_uint4(f2tf(v.x), f2tf(v.y), f2tf(v.z), f2tf(v.w));
                *(uint4*)((char*)(dst + (size_t)t * 8192) + swz(row * 128 + wq * 16)) = tv;
            }
        } else {
            // ---- zero stats ----
            #pragma unroll
            for (int i = 0; i < 4; i++) g_stats[tid + i * 256] = 0.0f;
        }
    } else {
        // ---- feat_prep: features [b][c][n] -> g_A1 tiles t=8..15 ----
        const int idx = blk - NB_3NN - NB_TFP - NB_MISC;
        const int n0 = (idx & 255) * 32;
        const int c0 = ((idx >> 8) & 7) * 32;
        const int b = idx >> 11;
        float (*tile)[33] = (float(*)[33])sm;
        const int tx = tid & 31, ty = tid >> 5;
        const float* src = feat + (size_t)b * CCH * NPT;
        #pragma unroll
        for (int j = 0; j < 32; j += 8)
            tile[ty + j][tx] = src[(size_t)(c0 + ty + j) * NPT + n0 + tx];
        __syncthreads();
        const int t = 8 + (c0 >> 5);
        #pragma unroll
        for (int j = 0; j < 32; j += 8) {
            const int p = b * NPT + n0 + ty + j;
            const int mblk = p >> 8, r = p & 255;
            uint32_t* blkp = g_A1 + ((size_t)mblk * NT1 + t) * 8192;
            *(uint32_t*)((char*)blkp + swz(r * 128 + tx * 4)) = f2tf(tile[tx][ty + j]);
        }
    }
}

// ---------------- interp(fpT, idx, wgt) -> g_A1 tiles t=0..7  (1 warp/point) ----------------
__global__ void k_interp_prep() {
    const int p = (blockIdx.x * blockDim.x + threadIdx.x) >> 5;
    const int lane = threadIdx.x & 31;
    const int b = p >> 13;
    const size_t o3 = (size_t)p * 3;
    const int i0 = g_idx[o3], i1 = g_idx[o3 + 1], i2 = g_idx[o3 + 2];
    const float w0 = g_wgt[o3], w1 = g_wgt[o3 + 1], w2 = g_wgt[o3 + 2];
    const float* fpb = g_fpT + (size_t)b * MPT * CPCH;
    const float* r0 = fpb + (size_t)i0 * CPCH;
    const float* r1 = fpb + (size_t)i1 * CPCH;
    const float* r2 = fpb + (size_t)i2 * CPCH;
    const int mblk = p >> 8, r = p & 255;
    #pragma unroll
    for (int t = 0; t < 8; t++) {
        const int c = t * 32 + lane;
        const float v = fmaf(w0, r0[c], fmaf(w1, r1[c], w2 * r2[c]));
        uint32_t* blk = g_A1 + ((size_t)mblk * NT1 + t) * 8192;
        *(uint32_t*)((char*)blk + swz(r * 128 + lane * 4)) = f2tf(v);
    }
}

// ---------------- tcgen05 TF32 GEMM, bulk-copy ring, M=256/CTA ----------------
// PHASE 1: A = g_A1; C -> g_A2 (pre-BN fp32, swizzled); stats -> g_stats[0..]
// PHASE 2: A = g_A2 with in-smem BN1+ReLU+tf32; C -> d_out [b][o][n]; stats -> g_stats[512..]
// smem map: 0 tmemptr | 16/24/32 full | 40/48/56 empty | 64 done | 256 sSum | 1280 sSq
//           2304 s_bnA | 3328 s_bnC | 8192.. stages (A 32KB + B 32KB per stage)
#define SM_STAGE0 8192u
#define SM_STAGEB 65536u
#define SM_TOTAL  (8192 + RING * 65536)

template <int PHASE>
__global__ void __launch_bounds__(256) k_tc_gemm(const float* __restrict__ bias,
                                                 float* __restrict__ Cout) {
    constexpr int NT = (PHASE == 1) ? NT1 : NT2;
    extern __shared__ char smem[];
    const int tid = threadIdx.x;
    const int mblk = blockIdx.x;
    const int statoff = (PHASE == 1) ? 0 : 512;

#if HAS_TCGEN05
    constexpr uint32_t IDESC =
        (1u << 4) | (2u << 7) | (2u << 10) | ((256u / 8) << 17) | ((128u / 16) << 24);
    const uint32_t sb = smem_u32(smem);
    const int w = tid >> 5;
    const uint32_t* Asrc = ((PHASE == 1) ? g_A1 : g_A2) + (size_t)mblk * NT * 8192;
    const uint32_t* Wsrc = (PHASE == 1) ? g_W1t : g_W2t;

    if (tid == 0) {
        #pragma unroll
        for (int s = 0; s < RING; s++) {
            asm volatile("mbarrier.init.shared.b64 [%0], 1;" :: "r"(sb + 16 + s * 8) : "memory");
            asm volatile("mbarrier.init.shared.b64 [%0], 1;" :: "r"(sb + 40 + s * 8) : "memory");
        }
        asm volatile("mbarrier.init.shared.b64 [%0], 1;" :: "r"(sb + 64) : "memory");
    }
    if (w == 0)
        asm volatile("tcgen05.alloc.cta_group::1.sync.aligned.shared::cta.b32 [%0], %1;"
                     :: "r"(sb), "r"(512u) : "memory");
    float* sSum = (float*)(smem + 256);
    float* sSq  = (float*)(smem + 1280);
    float* s_bnA = (float*)(smem + 2304);
    float* s_bnC = (float*)(smem + 3328);
    sSum[tid] = 0.f;
    sSq[tid]  = 0.f;
    if (PHASE == 2) { s_bnA[tid] = g_bnA[tid]; s_bnC[tid] = g_bnC[tid]; }
    __syncthreads();
    uint32_t tmem;
    asm volatile("ld.shared.b32 %0, [%1];" : "=r"(tmem) : "r"(sb));
    if (w == 0)
        asm volatile("tcgen05.relinquish_alloc_permit.cta_group::1.sync.aligned;");

    if (PHASE == 1) {
        // ---- warp-specialized: producer w0, consumer w1 ----
        if (w == 0 && elect1()) {
            int s = 0; uint32_t p = 1;
            for (int t = 0; t < NT; t++) {
                mbar_wait(sb + 40 + s * 8, p);
                asm volatile("mbarrier.arrive.expect_tx.shared.b64 _, [%0], %1;"
                             :: "r"(sb + 16 + s * 8), "r"(65536u) : "memory");
                bulk_g2s(sb + SM_STAGE0 + s * SM_STAGEB, Asrc + (size_t)t * 8192, 32768,
                         sb + 16 + s * 8);
                bulk_g2s(sb + SM_STAGE0 + s * SM_STAGEB + 32768, Wsrc + (size_t)t * 8192, 32768,
                         sb + 16 + s * 8);
                if (++s == RING) { s = 0; p ^= 1; }
            }
        } else if (w == 1 && elect1()) {
            int s = 0; uint32_t p = 0;
            for (int t = 0; t < NT; t++) {
                mbar_wait(sb + 16 + s * 8, p);
                const uint64_t ad = mk_desc(sb + SM_STAGE0 + s * SM_STAGEB);
                const uint64_t bd = mk_desc(sb + SM_STAGE0 + s * SM_STAGEB + 32768);
                #pragma unroll
                for (int h = 0; h < 2; h++)
                    #pragma unroll
                    for (int k = 0; k < 4; k++)
                        mma_tf32(tmem + h * 256, ad + h * 1024 + 2 * k, bd + 2 * k, IDESC,
                                 (uint32_t)((t | k) != 0));
                asm volatile(
                    "tcgen05.commit.cta_group::1.mbarrier::arrive::one.shared::cluster.b64 [%0];"
                    :: "r"(sb + 40 + s * 8) : "memory");
                if (++s == RING) { s = 0; p ^= 1; }
            }
            // unambiguous completion gate (in-order commit queue)
            asm volatile(
                "tcgen05.commit.cta_group::1.mbarrier::arrive::one.shared::cluster.b64 [%0];"
                :: "r"(sb + 64) : "memory");
        }
    } else {
        // ---- all-threads loop with in-smem BN1+ReLU+tf32 on A stages ----
        if (w == 0 && elect1()) {
            #pragma unroll
            for (int f = 0; f < RING; f++) {
                asm volatile("mbarrier.arrive.expect_tx.shared.b64 _, [%0], %1;"
                             :: "r"(sb + 16 + f * 8), "r"(65536u) : "memory");
                bulk_g2s(sb + SM_STAGE0 + f * SM_STAGEB, Asrc + (size_t)f * 8192, 32768,
                         sb + 16 + f * 8);
                bulk_g2s(sb + SM_STAGE0 + f * SM_STAGEB + 32768, Wsrc + (size_t)f * 8192, 32768,
                         sb + 16 + f * 8);
            }
        }
        for (int t = 0; t < NT; t++) {
            const int s = t % RING;
            const uint32_t pf = (uint32_t)((t / RING) & 1);
            mbar_wait(sb + 16 + s * 8, pf);              // all threads
            // transform A tile in place: fp32 -> relu(bn1) -> tf32
            char* stg = smem + SM_STAGE0 + s * SM_STAGEB;
            #pragma unroll
            for (int kq = 0; kq < 8; kq++) {
                const uint32_t b0 = (uint32_t)(tid + kq * 256) * 16;
                const uint32_t ch0 = ((b0 & 127u) ^ (((b0 >> 7) & 7u) << 4)) >> 2;
                const float4 a4 = *(const float4*)&s_bnA[t * 32 + ch0];
                const float4 c4 = *(const float4*)&s_bnC[t * 32 + ch0];
                uint4 x = *(uint4*)(stg + b0);
                float4 v = make_float4(__uint_as_float(x.x), __uint_as_float(x.y),
                                       __uint_as_float(x.z), __uint_as_float(x.w));
                v.x = fmaxf(fmaf(a4.x, v.x, c4.x), 0.f);
                v.y = fmaxf(fmaf(a4.y, v.y, c4.y), 0.f);
                v.z = fmaxf(fmaf(a4.z, v.z, c4.z), 0.f);
                v.w = fmaxf(fmaf(a4.w, v.w, c4.w), 0.f);
                *(uint4*)(stg + b0) = make_uint4(f2tf(v.x), f2tf(v.y), f2tf(v.z), f2tf(v.w));
            }
            asm volatile("fence.proxy.async.shared::cta;" ::: "memory");
            __syncthreads();
            if (w == 1 && elect1()) {
                const uint64_t ad = mk_desc(sb + SM_STAGE0 + s * SM_STAGEB);
                const uint64_t bd = mk_desc(sb + SM_STAGE0 + s * SM_STAGEB + 32768);
                #pragma unroll
                for (int h = 0; h < 2; h++)
                    #pragma unroll
                    for (int k = 0; k < 4; k++)
                        mma_tf32(tmem + h * 256, ad + h * 1024 + 2 * k, bd + 2 * k, IDESC,
                                 (uint32_t)((t | k) != 0));
                asm volatile(
                    "tcgen05.commit.cta_group::1.mbarrier::arrive::one.shared::cluster.b64 [%0];"
                    :: "r"(sb + 40 + s * 8) : "memory");
            }
            const int f = t + RING;
            if (f < NT && w == 0 && elect1()) {
                mbar_wait(sb + 40 + s * 8, (uint32_t)((t / RING) & 1));   // MMA t done
                asm volatile("mbarrier.arrive.expect_tx.shared.b64 _, [%0], %1;"
                             :: "r"(sb + 16 + s * 8), "r"(65536u) : "memory");
                bulk_g2s(sb + SM_STAGE0 + s * SM_STAGEB, Asrc + (size_t)f * 8192, 32768,
                         sb + 16 + s * 8);
                bulk_g2s(sb + SM_STAGE0 + s * SM_STAGEB + 32768, Wsrc + (size_t)f * 8192, 32768,
                         sb + 16 + s * 8);
            }
        }
        if (w == 1 && elect1()) {
            asm volatile(
                "tcgen05.commit.cta_group::1.mbarrier::arrive::one.shared::cluster.b64 [%0];"
                :: "r"(sb + 64) : "memory");
        }
    }

    mbar_wait(sb + 64, 0);         // all MMAs complete (in-order commits)
    asm volatile("tcgen05.fence::after_thread_sync;" ::: "memory");
    __syncthreads();

    // ---- epilogue: D (256x256 fp32, 2 halves) ----
    const int lane = tid & 31, sub = w & 3, h = w >> 2;
    float* redbuf = (float*)(smem + SM_STAGE0 + h * 17408);   // 128x33 per half
    #pragma unroll
    for (int cb = 0; cb < 8; cb++) {
        uint32_t rg[32];
        ldtm32(rg, tmem + ((uint32_t)sub << 21) + (uint32_t)(h * 256 + cb * 32));
        asm volatile("tcgen05.wait::ld.sync.aligned;" ::: "memory");
        const int col0 = cb * 32;
        float v[32];
        #pragma unroll
        for (int j = 0; j < 32; j++)
            v[j] = __uint_as_float(rg[j]) + __ldg(&bias[col0 + j]);
        if (PHASE == 2) {
            const int mrow = mblk * 256 + h * 128 + sub * 32 + lane;
            const int b = mrow >> 13, n = mrow & (NPT - 1);
            #pragma unroll
            for (int j = 0; j < 32; j++)
                Cout[((size_t)(b * OC + col0 + j)) * NPT + n] = v[j];
        }
        #pragma unroll
        for (int j = 0; j < 32; j++)
            redbuf[(sub * 32 + lane) * 33 + j] = v[j];
        __syncthreads();
        {
            float s = 0.f, q = 0.f;
            uint32_t* blk = g_A2 + ((size_t)mblk * NT2 + cb) * 8192;
            #pragma unroll
            for (int rr = 0; rr < 32; rr++) {
                const float x = redbuf[(sub * 32 + rr) * 33 + lane];
                s += x;
                q = fmaf(x, x, q);
                if (PHASE == 1) {
                    const int r = h * 128 + sub * 32 + rr;
                    *(uint32_t*)((char*)blk + ((uint32_t)(r * 128 + lane * 4) ^
                                               (((uint32_t)rr & 7u) << 4))) = __float_as_uint(x);
                }
            }
            atomicAdd(&sSum[col0 + lane], s);
            atomicAdd(&sSq[col0 + lane], q);
        }
        __syncthreads();
    }
    atomicAdd(&g_stats[statoff + tid], sSum[tid]);
    atomicAdd(&g_stats[statoff + 256 + tid], sSq[tid]);
    __syncthreads();
    if (tid == 0) {
        #pragma unroll
        for (int s = 0; s < RING; s++) {
            asm volatile("mbarrier.inval.shared.b64 [%0];" :: "r"(sb + 16 + s * 8) : "memory");
            asm volatile("mbarrier.inval.shared.b64 [%0];" :: "r"(sb + 40 + s * 8) : "memory");
        }
        asm volatile("mbarrier.inval.shared.b64 [%0];" :: "r"(sb + 64) : "memory");
    }
    __syncthreads();
    if (w == 0)
        asm volatile("tcgen05.dealloc.cta_group::1.sync.aligned.b32 %0, %1;"
                     :: "r"(tmem), "r"(512u));

#else
    // ---- portable FFMA fallback (non-'a' target only; never selected on GB300) ----
    (void)smem;
    constexpr int K = (PHASE == 1) ? KD1 : OC;
    const uint32_t* Ablk = ((PHASE == 1) ? g_A1 : g_A2) + (size_t)mblk * ((PHASE == 1) ? NT1 : NT2) * 8192;
    const uint32_t* Wblk = (PHASE == 1) ? g_W1t : g_W2t;
    const int ty = tid >> 4, tx = tid & 15;
    for (int cc = 0; cc < 16; cc++) {
        const int col = tx * 16 + cc;
        float acc[16];
        #pragma unroll
        for (int i = 0; i < 16; i++) acc[i] = 0.f;
        for (int k = 0; k < K; k++) {
            const int t = k >> 5, ww = k & 31;
            const float bv = __uint_as_float(
                Wblk[(size_t)t * 8192 + (swz((uint32_t)(col * 128 + ww * 4)) >> 2)]);
            #pragma unroll
            for (int i = 0; i < 16; i++) {
                const int r = ty * 16 + i;
                float av = __uint_as_float(
                    Ablk[(size_t)t * 8192 + (swz((uint32_t)(r * 128 + ww * 4)) >> 2)]);
                if (PHASE == 2)
                    av = fmaxf(fmaf(g_bnA[k], av, g_bnC[k]), 0.f);
                acc[i] = fmaf(av, bv, acc[i]);
            }
        }
        const float bb = bias[col];
        #pragma unroll
        for (int i = 0; i < 16; i++) {
            const int r = ty * 16 + i;
            const float val = acc[i] + bb;
            if (PHASE == 1) {
                uint32_t* blk = g_A2 + ((size_t)mblk * NT2 + (col >> 5)) * 8192;
                *(uint32_t*)((char*)blk + swz((uint32_t)(r * 128 + (col & 31) * 4))) =
                    __float_as_uint(val);
            } else {
                const int mrow = mblk * 256 + r;
                const int b = mrow >> 13, n = mrow & (NPT - 1);
                Cout[((size_t)(b * OC + col)) * NPT + n] = val;
            }
            atomicAdd(&g_stats[statoff + col], val);
            atomicAdd(&g_stats[statoff + 256 + col], val * val);
        }
    }
#endif
}

// ---------------- BN finalize ----------------
__global__ void k_bn_final(const float* __restrict__ g, const float* __restrict__ beta, int layer) {
    const int c = threadIdx.x;
    const float invn = 1.0f / (float)NPOINTS;
    const float s = g_stats[layer * 512 + c];
    const float q = g_stats[layer * 512 + 256 + c];
    const float mean = s * invn;
    const float var = q * invn - mean * mean;
    const float a = g[c] * rsqrtf(var + BN_EPS);
    g_bnA[layer * 256 + c] = a;
    g_bnC[layer * 256 + c] = beta[c] - mean * a;
}

// ---------------- final in-place BN2 + ReLU over d_out [b][c][n] ----------------
__global__ void k_bn_relu_out(float* __restrict__ out) {
    const size_t i = (size_t)blockIdx.x * blockDim.x + threadIdx.x;
    const int ch = (int)((i >> 11) & 255);
    const float a = g_bnA[256 + ch];
    const float c = g_bnC[256 + ch];
    float4 v = ((float4*)out)[i];
    v.x = fmaxf(fmaf(a, v.x, c), 0.f);
    v.y = fmaxf(fmaf(a, v.y, c), 0.f);
    v.z = fmaxf(fmaf(a, v.z, c), 0.f);
    v.w = fmaxf(fmaf(a, v.w, c), 0.f);
    ((float4*)out)[i] = v;
}

// ---------------- launch ----------------
extern "C" void kernel_launch(void* const* d_in, const int* in_sizes, int n_in,
                              void* d_out, int out_size) {
    const float* xyz   = (const float*)d_in[0];
    const float* xyzp  = (const float*)d_in[1];
    const float* feat  = (const float*)d_in[2];
    const float* featp = (const float*)d_in[3];
    const float* w1    = (const float*)d_in[4];
    const float* b1    = (const float*)d_in[5];
    const float* g1    = (const float*)d_in[6];
    const float* be1   = (const float*)d_in[7];
    const float* w2    = (const float*)d_in[8];
    const float* b2    = (const float*)d_in[9];
    const float* g2    = (const float*)d_in[10];
    const float* be2   = (const float*)d_in[11];
    float* out = (float*)d_out;

    cudaFuncSetAttribute((const void*)k_tc_gemm<1>,
                         cudaFuncAttributeMaxDynamicSharedMemorySize, SM_TOTAL);
    cudaFuncSetAttribute((const void*)k_tc_gemm<2>,
                         cudaFuncAttributeMaxDynamicSharedMemorySize, SM_TOTAL);

    k_prep<<<NB_TOTAL, 256>>>(xyz, xyzp, featp, feat, w1, w2);
    k_interp_prep<<<(NPOINTS * 32) / 256, 256>>>();

    k_tc_gemm<1><<<NMBLK, 256, SM_TOTAL>>>(b1, nullptr);
    k_bn_final<<<1, 256>>>(g1, be1, 0);

    k_tc_gemm<2><<<NMBLK, 256, SM_TOTAL>>>(b2, out);
    k_bn_final<<<1, 256>>>(g2, be2, 1);
    k_bn_relu_out<<<(NPOINTS * OC / 4) / 256, 256>>>(out);
}

// round 14
// speedup vs baseline: 1.4091x; 1.4091x over previous
#include <cuda_runtime.h>
#include <cstdint>
#include <math.h>

// Problem constants
#define BB   8
#define NPT  8192
#define MPT  2048
#define CCH  256
#define CPCH 256
#define KD1  512
#define OC   256
#define NPOINTS (BB * NPT)   // 65536
#define BN_EPS 1e-5f
#define NMBLK (NPOINTS / 256)   // 256 m-blocks of 256 points
#define NT1  16                 // K-chunks GEMM1 (512/32)
#define NT2  8                  // K-chunks GEMM2 (256/32)
#define RING 3

#if defined(__CUDA_ARCH_FEAT_SM103_ALL) || defined(__CUDA_ARCH_FEAT_SM100_ALL)
#define HAS_TCGEN05 1
#else
#define HAS_TCGEN05 0
#endif

// ---------------- scratch (device globals; no allocs allowed) ----------------
// Swizzled tile images: block = [256 rows][32 k-words], 32KB, SW128 per 128B row.
__device__ __align__(16) uint32_t g_A1[(size_t)NMBLK * NT1 * 8192];  // tf32
__device__ __align__(16) uint32_t g_A2[(size_t)NMBLK * NT2 * 8192];  // fp32 pre-BN -> tf32
__device__ __align__(16) uint32_t g_W1t[NT1 * 8192];
__device__ __align__(16) uint32_t g_W2t[NT2 * 8192];
__device__ __align__(16) float g_fpT[(size_t)BB * MPT * CPCH];       // features_prev^T [b][m][c]
__device__ int   g_idx[(size_t)NPOINTS * 3];
__device__ float g_wgt[(size_t)NPOINTS * 3];
__device__ __align__(16) float g_stats[4 * 256];
__device__ __align__(16) float g_bnA[2 * 256];   // used by non-tcgen05 fallback only
__device__ __align__(16) float g_bnC[2 * 256];

// ---------------- helpers ----------------
__device__ __forceinline__ uint32_t smem_u32(const void* p) {
    uint32_t a;
    asm("{ .reg .u64 t; cvta.to.shared.u64 t, %1; cvt.u32.u64 %0, t; }" : "=r"(a) : "l"(p));
    return a;
}
__device__ __host__ __forceinline__ uint32_t swz(uint32_t o) { return o ^ ((o >> 3) & 0x70); }
__device__ __forceinline__ uint32_t f2tf(float f) {
    uint32_t r; asm("cvt.rna.tf32.f32 %0, %1;" : "=r"(r) : "f"(f)); return r;
}

#if HAS_TCGEN05
__device__ __forceinline__ uint32_t elect1() {
    uint32_t p;
    asm volatile("{ .reg .pred p; elect.sync _|p, 0xFFFFFFFF; selp.b32 %0,1,0,p; }" : "=r"(p));
    return p;
}
static constexpr uint64_t DESC_BASE =
    (2ull << 61) | (1ull << 46) | (64ull << 32) | (1ull << 16);   // SW128, Blackwell, SBO=64, LBO=1
__device__ __forceinline__ uint64_t mk_desc(uint32_t a) {
    return DESC_BASE | (uint64_t)((a >> 4) & 0x3FFF);
}
__device__ __forceinline__ void mma_tf32(uint32_t d, uint64_t a, uint64_t b,
                                         uint32_t idesc, uint32_t en) {
    asm volatile(
        "{\n\t.reg .pred p;\n\tsetp.ne.u32 p, %5, 0;\n\t"
        "tcgen05.mma.cta_group::1.kind::tf32 [%0], %1, %2, %3, {%4, %4, %4, %4}, p;\n\t}"
        :: "r"(d), "l"(a), "l"(b), "r"(idesc), "r"(0u), "r"(en) : "memory");
}
__device__ __forceinline__ void mbar_wait(uint32_t mbar, uint32_t parity) {
    asm volatile(
        "{\n\t.reg .pred P;\n\tLW_%=:\n\t"
        "mbarrier.try_wait.parity.acquire.cta.shared::cta.b64 P, [%0], %1, 0x989680;\n\t"
        "@P bra.uni LD_%=;\n\tbra.uni LW_%=;\n\tLD_%=:\n\t}"
        :: "r"(mbar), "r"(parity) : "memory");
}
__device__ __forceinline__ void bulk_g2s(uint32_t dst, const void* src, uint32_t bytes,
                                         uint32_t mbar) {
    asm volatile(
        "cp.async.bulk.shared::cluster.global.mbarrier::complete_tx::bytes [%0], [%1], %2, [%3];"
        :: "r"(dst), "l"(src), "r"(bytes), "r"(mbar) : "memory");
}
__device__ __forceinline__ void ldtm32(uint32_t* r, uint32_t addr) {
    asm volatile(
        "tcgen05.ld.sync.aligned.32x32b.x32.b32 "
        "{%0, %1, %2, %3, %4, %5, %6, %7, %8, %9, %10, %11, %12, %13, %14, %15, "
        " %16, %17, %18, %19, %20, %21, %22, %23, %24, %25, %26, %27, %28, %29, %30, %31}, [%32];"
        : "=r"(r[0]), "=r"(r[1]), "=r"(r[2]), "=r"(r[3]), "=r"(r[4]), "=r"(r[5]),
          "=r"(r[6]), "=r"(r[7]), "=r"(r[8]), "=r"(r[9]), "=r"(r[10]), "=r"(r[11]),
          "=r"(r[12]), "=r"(r[13]), "=r"(r[14]), "=r"(r[15]), "=r"(r[16]), "=r"(r[17]),
          "=r"(r[18]), "=r"(r[19]), "=r"(r[20]), "=r"(r[21]), "=r"(r[22]), "=r"(r[23]),
          "=r"(r[24]), "=r"(r[25]), "=r"(r[26]), "=r"(r[27]), "=r"(r[28]), "=r"(r[29]),
          "=r"(r[30]), "=r"(r[31])
        : "r"(addr));
}
#endif  // HAS_TCGEN05

// ---------------- three_nn (own launch; long-running LDS-bound blocks) ----------------
__global__ void k_three_nn(const float* __restrict__ xyz, const float* __restrict__ xyzp) {
    const int b = blockIdx.y;
    const int n = blockIdx.x * 256 + threadIdx.x;
    __shared__ float4 sk[MPT];
    const float* kp = xyzp + (size_t)b * MPT * 3;
    for (int m = threadIdx.x; m < MPT; m += 256) {
        float kx = kp[3 * m], ky = kp[3 * m + 1], kz = kp[3 * m + 2];
        sk[m] = make_float4(kx, ky, kz, kx * kx + ky * ky + kz * kz);
    }
    __syncthreads();
    const float* up = xyz + (size_t)(b * NPT + n) * 3;
    float ux = up[0], uy = up[1], uz = up[2];
    float squ = ux * ux + uy * uy + uz * uz;
    float d0 = 3.4e38f, d1 = 3.4e38f, d2 = 3.4e38f;
    int i0 = 0, i1 = 0, i2 = 0;
    for (int m = 0; m < MPT; m++) {
        float4 k = sk[m];
        float dot = fmaf(ux, k.x, fmaf(uy, k.y, uz * k.z));
        float dd = squ + k.w - 2.0f * dot;
        if (dd < d2) {
            if (dd < d1) {
                d2 = d1; i2 = i1;
                if (dd < d0) { d1 = d0; i1 = i0; d0 = dd; i0 = m; }
                else         { d1 = dd; i1 = m; }
            } else { d2 = dd; i2 = m; }
        }
    }
    float s0 = sqrtf(fmaxf(d0, 0.f)), s1 = sqrtf(fmaxf(d1, 0.f)), s2 = sqrtf(fmaxf(d2, 0.f));
    float w0 = 1.0f / (s0 + 1e-8f), w1 = 1.0f / (s1 + 1e-8f), w2 = 1.0f / (s2 + 1e-8f);
    float ws = w0 + w1 + w2;
    size_t o = (size_t)(b * NPT + n) * 3;
    g_idx[o] = i0; g_idx[o + 1] = i1; g_idx[o + 2] = i2;
    g_wgt[o] = w0 / ws; g_wgt[o + 1] = w1 / ws; g_wgt[o + 2] = w2 / ws;
}

// ======= merged prep: transpose_fp | w_prep | zero_stats | feat_prep (all short blocks) =======
#define NB_TFP  4096
#define NB_MISC 25            // 16 w1 + 8 w2 + 1 zero
#define NB_FEAT 16384
#define NB_PREP (NB_TFP + NB_MISC + NB_FEAT)   // 20505

__global__ void __launch_bounds__(256) k_prep_merged(
    const float* __restrict__ featp, const float* __restrict__ feat,
    const float* __restrict__ w1, const float* __restrict__ w2) {
    __shared__ float tile[32][33];
    const int blk = blockIdx.x;
    const int tid = threadIdx.x;

    if (blk < NB_TFP) {
        // ---- transpose features_prev [b][c][m] -> g_fpT [b][m][c] ----
        const int m0 = (blk & 63) * 32;
        const int c0 = ((blk >> 6) & 7) * 32;
        const int b = blk >> 9;
        const int tx = tid & 31, ty = tid >> 5;   // 32 x 8
        const float* src = featp + (size_t)b * CPCH * MPT;
        #pragma unroll
        for (int j = 0; j < 32; j += 8)
            tile[ty + j][tx] = src[(size_t)(c0 + ty + j) * MPT + m0 + tx];
        __syncthreads();
        float* dst = g_fpT + (size_t)b * MPT * CPCH;
        #pragma unroll
        for (int j = 0; j < 32; j += 8)
            dst[(size_t)(m0 + ty + j) * CPCH + c0 + tx] = tile[tx][ty + j];
    } else if (blk < NB_TFP + NB_MISC) {
        const int idx = blk - NB_TFP;
        if (idx < 24) {
            // ---- w_prep: swizzled tf32 weight tiles ----
            const int t = (idx < 16) ? idx : (idx - 16);
            const float* W = (idx < 16) ? w1 : w2;
            const int K = (idx < 16) ? KD1 : OC;
            uint32_t* dst = (idx < 16) ? g_W1t : g_W2t;
            #pragma unroll
            for (int i = 0; i < 8; i++) {
                const int f = tid + i * 256;
                const int row = f >> 3, wq = f & 7;
                const float4 v = *(const float4*)(W + (size_t)row * K + t * 32 + wq * 4);
                uint4 tv = make_uint4(f2tf(v.x), f2tf(v.y), f2tf(v.z), f2tf(v.w));
                *(uint4*)((char*)(dst + (size_t)t * 8192) + swz(row * 128 + wq * 16)) = tv;
            }
        } else {
            // ---- zero stats ----
            #pragma unroll
            for (int i = 0; i < 4; i++) g_stats[tid + i * 256] = 0.0f;
        }
    } else {
        // ---- feat_prep: features [b][c][n] -> g_A1 tiles t=8..15 ----
        const int idx = blk - NB_TFP - NB_MISC;
        const int n0 = (idx & 255) * 32;
        const int c0 = ((idx >> 8) & 7) * 32;
        const int b = idx >> 11;
        const int tx = tid & 31, ty = tid >> 5;
        const float* src = feat + (size_t)b * CCH * NPT;
        #pragma unroll
        for (int j = 0; j < 32; j += 8)
            tile[ty + j][tx] = src[(size_t)(c0 + ty + j) * NPT + n0 + tx];
        __syncthreads();
        const int t = 8 + (c0 >> 5);
        #pragma unroll
        for (int j = 0; j < 32; j += 8) {
            const int p = b * NPT + n0 + ty + j;
            const int mblk = p >> 8, r = p & 255;
            uint32_t* blkp = g_A1 + ((size_t)mblk * NT1 + t) * 8192;
            *(uint32_t*)((char*)blkp + swz(r * 128 + tx * 4)) = f2tf(tile[tx][ty + j]);
        }
    }
}

// ---------------- interp(fpT, idx, wgt) -> g_A1 tiles t=0..7  (1 warp/point) ----------------
__global__ void k_interp_prep() {
    const int p = (blockIdx.x * blockDim.x + threadIdx.x) >> 5;
    const int lane = threadIdx.x & 31;
    const int b = p >> 13;
    const size_t o3 = (size_t)p * 3;
    const int i0 = g_idx[o3], i1 = g_idx[o3 + 1], i2 = g_idx[o3 + 2];
    const float w0 = g_wgt[o3], w1 = g_wgt[o3 + 1], w2 = g_wgt[o3 + 2];
    const float* fpb = g_fpT + (size_t)b * MPT * CPCH;
    const float* r0 = fpb + (size_t)i0 * CPCH;
    const float* r1 = fpb + (size_t)i1 * CPCH;
    const float* r2 = fpb + (size_t)i2 * CPCH;
    const int mblk = p >> 8, r = p & 255;
    #pragma unroll
    for (int t = 0; t < 8; t++) {
        const int c = t * 32 + lane;
        const float v = fmaf(w0, r0[c], fmaf(w1, r1[c], w2 * r2[c]));
        uint32_t* blk = g_A1 + ((size_t)mblk * NT1 + t) * 8192;
        *(uint32_t*)((char*)blk + swz(r * 128 + lane * 4)) = f2tf(v);
    }
}

// ---------------- in-place BN1 + ReLU + tf32 over g_A2 (inline coefficients) ----------------
__global__ void k_bn1_prep(const float* __restrict__ g1, const float* __restrict__ be1) {
    const size_t i = (size_t)blockIdx.x * blockDim.x + threadIdx.x;   // uint4 index
    const uint32_t byte = (uint32_t)((i * 16) & 32767);
    const size_t blk = (i * 16) >> 15;
    const int t2 = (int)(blk & 7);
    const int r = byte >> 7;
    const uint32_t u = (byte >> 4) & 7;
    const int wg = (int)((u ^ (r & 7)) << 2);                         // original word group
    const int ch0 = t2 * 32 + wg;
    const float invn = 1.0f / (float)NPOINTS;
    float a[4], c[4];
    #pragma unroll
    for (int j = 0; j < 4; j++) {
        const float s = g_stats[ch0 + j];
        const float q = g_stats[256 + ch0 + j];
        const float mean = s * invn;
        const float var = q * invn - mean * mean;
        const float aa = g1[ch0 + j] * rsqrtf(var + BN_EPS);
        a[j] = aa;
        c[j] = be1[ch0 + j] - mean * aa;
    }
    uint4 x = ((const uint4*)g_A2)[i];
    float4 v = make_float4(__uint_as_float(x.x), __uint_as_float(x.y),
                           __uint_as_float(x.z), __uint_as_float(x.w));
    v.x = fmaxf(fmaf(a[0], v.x, c[0]), 0.f);
    v.y = fmaxf(fmaf(a[1], v.y, c[1]), 0.f);
    v.z = fmaxf(fmaf(a[2], v.z, c[2]), 0.f);
    v.w = fmaxf(fmaf(a[3], v.w, c[3]), 0.f);
    ((uint4*)g_A2)[i] = make_uint4(f2tf(v.x), f2tf(v.y), f2tf(v.z), f2tf(v.w));
}

// ---------------- tcgen05 TF32 GEMM, bulk-copy ring, M=256/CTA (round-12 verbatim) ----------------
#define SM_STAGE0 4096u
#define SM_STAGEB 65536u
#define SM_TOTAL  (4096 + RING * 65536)

template <int PHASE>
__global__ void __launch_bounds__(256) k_tc_gemm(const float* __restrict__ bias,
                                                 float* __restrict__ Cout) {
    constexpr int NT = (PHASE == 1) ? NT1 : NT2;
    extern __shared__ char smem[];
    const int tid = threadIdx.x;
    const int mblk = blockIdx.x;
    const int statoff = (PHASE == 1) ? 0 : 512;

#if HAS_TCGEN05
    constexpr uint32_t IDESC =
        (1u << 4) | (2u << 7) | (2u << 10) | ((256u / 8) << 17) | ((128u / 16) << 24);
    const uint32_t sb = smem_u32(smem);
    const int w = tid >> 5;
    const uint32_t* Asrc = ((PHASE == 1) ? g_A1 : g_A2) + (size_t)mblk * NT * 8192;
    const uint32_t* Wsrc = (PHASE == 1) ? g_W1t : g_W2t;

    if (tid == 0) {
        #pragma unroll
        for (int s = 0; s < RING; s++) {
            asm volatile("mbarrier.init.shared.b64 [%0], 1;" :: "r"(sb + 16 + s * 8) : "memory");
            asm volatile("mbarrier.init.shared.b64 [%0], 1;" :: "r"(sb + 40 + s * 8) : "memory");
        }
    }
    if (w == 0)
        asm volatile("tcgen05.alloc.cta_group::1.sync.aligned.shared::cta.b32 [%0], %1;"
                     :: "r"(sb), "r"(512u) : "memory");
    float* sSum = (float*)(smem + 256);
    float* sSq  = (float*)(smem + 1280);
    sSum[tid] = 0.f;
    sSq[tid]  = 0.f;
    __syncthreads();
    uint32_t tmem;
    asm volatile("ld.shared.b32 %0, [%1];" : "=r"(tmem) : "r"(sb));
    if (w == 0)
        asm volatile("tcgen05.relinquish_alloc_permit.cta_group::1.sync.aligned;");

    if (w == 0 && elect1()) {
        // producer: bulk-copy A (32KB) + B (32KB) per tile
        int s = 0; uint32_t p = 1;
        for (int t = 0; t < NT; t++) {
            mbar_wait(sb + 40 + s * 8, p);
            asm volatile("mbarrier.arrive.expect_tx.shared.b64 _, [%0], %1;"
                         :: "r"(sb + 16 + s * 8), "r"(65536u) : "memory");
            bulk_g2s(sb + SM_STAGE0 + s * SM_STAGEB, Asrc + (size_t)t * 8192, 32768,
                     sb + 16 + s * 8);
            bulk_g2s(sb + SM_STAGE0 + s * SM_STAGEB + 32768, Wsrc + (size_t)t * 8192, 32768,
                     sb + 16 + s * 8);
            if (++s == RING) { s = 0; p ^= 1; }
        }
    } else if (w == 1 && elect1()) {
        // consumer: MMA
        int s = 0; uint32_t p = 0;
        for (int t = 0; t < NT; t++) {
            mbar_wait(sb + 16 + s * 8, p);
            const uint64_t ad = mk_desc(sb + SM_STAGE0 + s * SM_STAGEB);
            const uint64_t bd = mk_desc(sb + SM_STAGE0 + s * SM_STAGEB + 32768);
            #pragma unroll
            for (int h = 0; h < 2; h++)
                #pragma unroll
                for (int k = 0; k < 4; k++)
                    mma_tf32(tmem + h * 256, ad + h * 1024 + 2 * k, bd + 2 * k, IDESC,
                             (uint32_t)((t | k) != 0));
            asm volatile(
                "tcgen05.commit.cta_group::1.mbarrier::arrive::one.shared::cluster.b64 [%0];"
                :: "r"(sb + 40 + s * 8) : "memory");
            if (++s == RING) { s = 0; p ^= 1; }
        }
    }
    // gate: last commit (ordered after all MMAs) on empty[slast]
    {
        const int slast = (NT - 1) % RING;
        const uint32_t plast = (uint32_t)(((NT - 1 - slast) / RING) & 1);
        mbar_wait(sb + 40 + slast * 8, plast);
    }
    asm volatile("tcgen05.fence::after_thread_sync;" ::: "memory");
    __syncthreads();

    // ---- epilogue: D (256x256 fp32, 2 halves) ----
    const int lane = tid & 31, sub = w & 3, h = w >> 2;
    float* redbuf = (float*)(smem + SM_STAGE0 + h * 17408);   // 128x33 per half
    #pragma unroll
    for (int cb = 0; cb < 8; cb++) {
        uint32_t rg[32];
        ldtm32(rg, tmem + ((uint32_t)sub << 21) + (uint32_t)(h * 256 + cb * 32));
        asm volatile("tcgen05.wait::ld.sync.aligned;" ::: "memory");
        const int col0 = cb * 32;
        float v[32];
        #pragma unroll
        for (int j = 0; j < 32; j++)
            v[j] = __uint_as_float(rg[j]) + __ldg(&bias[col0 + j]);
        if (PHASE == 2) {
            const int mrow = mblk * 256 + h * 128 + sub * 32 + lane;
            const int b = mrow >> 13, n = mrow & (NPT - 1);
            #pragma unroll
            for (int j = 0; j < 32; j++)
                Cout[((size_t)(b * OC + col0 + j)) * NPT + n] = v[j];
        }
        #pragma unroll
        for (int j = 0; j < 32; j++)
            redbuf[(sub * 32 + lane) * 33 + j] = v[j];
        __syncthreads();
        {
            float s = 0.f, q = 0.f;
            uint32_t* blk = g_A2 + ((size_t)mblk * NT2 + cb) * 8192;
            #pragma unroll
            for (int rr = 0; rr < 32; rr++) {
                const float x = redbuf[(sub * 32 + rr) * 33 + lane];
                s += x;
                q = fmaf(x, x, q);
                if (PHASE == 1) {
                    const int r = h * 128 + sub * 32 + rr;
                    *(uint32_t*)((char*)blk + ((uint32_t)(r * 128 + lane * 4) ^
                                               (((uint32_t)rr & 7u) << 4))) = __float_as_uint(x);
                }
            }
            atomicAdd(&sSum[col0 + lane], s);
            atomicAdd(&sSq[col0 + lane], q);
        }
        __syncthreads();
    }
    atomicAdd(&g_stats[statoff + tid], sSum[tid]);
    atomicAdd(&g_stats[statoff + 256 + tid], sSq[tid]);
    __syncthreads();
    if (tid == 0) {
        #pragma unroll
        for (int s = 0; s < RING; s++) {
            asm volatile("mbarrier.inval.shared.b64 [%0];" :: "r"(sb + 16 + s * 8) : "memory");
            asm volatile("mbarrier.inval.shared.b64 [%0];" :: "r"(sb + 40 + s * 8) : "memory");
        }
    }
    __syncthreads();
    if (w == 0)
        asm volatile("tcgen05.dealloc.cta_group::1.sync.aligned.b32 %0, %1;"
                     :: "r"(tmem), "r"(512u));

#else
    // ---- portable FFMA fallback (non-'a' target only; never selected on GB300) ----
    (void)smem;
    constexpr int K = (PHASE == 1) ? KD1 : OC;
    const uint32_t* Ablk = ((PHASE == 1) ? g_A1 : g_A2) + (size_t)mblk * ((PHASE == 1) ? NT1 : NT2) * 8192;
    const uint32_t* Wblk = (PHASE == 1) ? g_W1t : g_W2t;
    const int ty = tid >> 4, tx = tid & 15;
    for (int cc = 0; cc < 16; cc++) {
        const int col = tx * 16 + cc;
        float acc[16];
        #pragma unroll
        for (int i = 0; i < 16; i++) acc[i] = 0.f;
        for (int k = 0; k < K; k++) {
            const int t = k >> 5, ww = k & 31;
            const float bv = __uint_as_float(
                Wblk[(size_t)t * 8192 + (swz((uint32_t)(col * 128 + ww * 4)) >> 2)]);
            #pragma unroll
            for (int i = 0; i < 16; i++) {
                const int r = ty * 16 + i;
                float av = __uint_as_float(
                    Ablk[(size_t)t * 8192 + (swz((uint32_t)(r * 128 + ww * 4)) >> 2)]);
                acc[i] = fmaf(av, bv, acc[i]);
            }
        }
        const float bb = bias[col];
        #pragma unroll
        for (int i = 0; i < 16; i++) {
            const int r = ty * 16 + i;
            const float val = acc[i] + bb;
            if (PHASE == 1) {
                uint32_t* blk = g_A2 + ((size_t)mblk * NT2 + (col >> 5)) * 8192;
                *(uint32_t*)((char*)blk + swz((uint32_t)(r * 128 + (col & 31) * 4))) =
                    __float_as_uint(val);
            } else {
                const int mrow = mblk * 256 + r;
                const int b = mrow >> 13, n = mrow & (NPT - 1);
                Cout[((size_t)(b * OC + col)) * NPT + n] = val;
            }
            atomicAdd(&g_stats[statoff + col], val);
            atomicAdd(&g_stats[statoff + 256 + col], val * val);
        }
    }
#endif
}

// ---------------- final in-place BN2 + ReLU over d_out [b][c][n] (inline coefficients) ------
__global__ void k_bn_relu_out(float* __restrict__ out,
                              const float* __restrict__ g2, const float* __restrict__ be2) {
    const size_t i = (size_t)blockIdx.x * blockDim.x + threadIdx.x;
    const int ch = (int)((i >> 11) & 255);
    const float invn = 1.0f / (float)NPOINTS;
    const float s = g_stats[512 + ch];
    const float q = g_stats[768 + ch];
    const float mean = s * invn;
    const float var = q * invn - mean * mean;
    const float a = g2[ch] * rsqrtf(var + BN_EPS);
    const float c = be2[ch] - mean * a;
    float4 v = ((float4*)out)[i];
    v.x = fmaxf(fmaf(a, v.x, c), 0.f);
    v.y = fmaxf(fmaf(a, v.y, c), 0.f);
    v.z = fmaxf(fmaf(a, v.z, c), 0.f);
    v.w = fmaxf(fmaf(a, v.w, c), 0.f);
    ((float4*)out)[i] = v;
}

// ---------------- launch ----------------
extern "C" void kernel_launch(void* const* d_in, const int* in_sizes, int n_in,
                              void* d_out, int out_size) {
    const float* xyz   = (const float*)d_in[0];
    const float* xyzp  = (const float*)d_in[1];
    const float* feat  = (const float*)d_in[2];
    const float* featp = (const float*)d_in[3];
    const float* w1    = (const float*)d_in[4];
    const float* b1    = (const float*)d_in[5];
    const float* g1    = (const float*)d_in[6];
    const float* be1   = (const float*)d_in[7];
    const float* w2    = (const float*)d_in[8];
    const float* b2    = (const float*)d_in[9];
    const float* g2    = (const float*)d_in[10];
    const float* be2   = (const float*)d_in[11];
    float* out = (float*)d_out;

    cudaFuncSetAttribute((const void*)k_tc_gemm<1>,
                         cudaFuncAttributeMaxDynamicSharedMemorySize, SM_TOTAL);
    cudaFuncSetAttribute((const void*)k_tc_gemm<2>,
                         cudaFuncAttributeMaxDynamicSharedMemorySize, SM_TOTAL);

    k_three_nn<<<dim3(NPT / 256, BB), 256>>>(xyz, xyzp);                 // 0
    k_prep_merged<<<NB_PREP, 256>>>(featp, feat, w1, w2);                // 1
    k_interp_prep<<<(NPOINTS * 32) / 256, 256>>>();                      // 2
    k_tc_gemm<1><<<NMBLK, 256, SM_TOTAL>>>(b1, nullptr);                 // 3
    k_bn1_prep<<<(int)(((size_t)NMBLK * NT2 * 8192 / 4) / 256), 256>>>(g1, be1);  // 4
    k_tc_gemm<2><<<NMBLK, 256, SM_TOTAL>>>(b2, out);                     // 5  <- ncu -s 5 captures this
    k_bn_relu_out<<<(NPOINTS * OC / 4) / 256, 256>>>(out, g2, be2);      // 6
}